// round 1
// baseline (speedup 1.0000x reference)
#include <cuda_runtime.h>
#include <cuda_bf16.h>

// Problem constants
#define T_SEQ  2048
#define NHEAD  16
#define HDIM   1024
#define HD     64
#define BATCH  2
#define MROWS  (BATCH * T_SEQ)   // 4096

// Scratch (device globals; no allocations allowed)
__device__ float g_qkv[MROWS * 3 * HDIM];            // 50.3 MB
__device__ float g_Q[BATCH * NHEAD * T_SEQ * HD];    // 16.8 MB
__device__ float g_K[BATCH * NHEAD * T_SEQ * HD];
__device__ float g_V[BATCH * NHEAD * T_SEQ * HD];
__device__ float g_attn[MROWS * HDIM];               // 16.8 MB

// ---------------------------------------------------------------------------
// Tiled SGEMM: C[M,N] = A[M,K] @ B[K,N] (+ bias). BM=BN=64, BK=16, 256 thr,
// 4x4 micro-tile per thread. All dims divisible by tiles (no guards).
// ---------------------------------------------------------------------------
#define BM 64
#define BN 64
#define BK 16

__global__ __launch_bounds__(256) void sgemm_bias(
    const float* __restrict__ A, const float* __restrict__ B,
    const float* __restrict__ bias, float* __restrict__ C,
    int M, int N, int K)
{
    __shared__ float As[BK][BM + 4];   // [k][m], padded
    __shared__ float Bs[BK][BN];       // [k][n]

    const int tid = threadIdx.x;
    const int ty = tid >> 4, tx = tid & 15;
    const int bm = blockIdx.y * BM, bn = blockIdx.x * BN;

    // Load mapping
    const int am = tid >> 2;           // 0..63  (row in A tile)
    const int ak = (tid & 3) << 2;     // 0,4,8,12
    const int bk = tid >> 4;           // 0..15  (row in B tile)
    const int bn4 = (tid & 15) << 2;   // 0..60

    const float* Aptr = A + (size_t)(bm + am) * K + ak;
    const float* Bptr = B + (size_t)bk * N + bn + bn4;

    float acc[4][4] = {};

    for (int k0 = 0; k0 < K; k0 += BK) {
        float4 a = *(const float4*)Aptr;  Aptr += BK;
        float4 bv = *(const float4*)Bptr; Bptr += (size_t)BK * N;

        __syncthreads();
        As[ak + 0][am] = a.x;
        As[ak + 1][am] = a.y;
        As[ak + 2][am] = a.z;
        As[ak + 3][am] = a.w;
        *(float4*)&Bs[bk][bn4] = bv;
        __syncthreads();

#pragma unroll
        for (int kk = 0; kk < BK; kk++) {
            float ra[4], rb[4];
            *(float4*)ra = *(const float4*)&As[kk][ty << 2];
            *(float4*)rb = *(const float4*)&Bs[kk][tx << 2];
#pragma unroll
            for (int i = 0; i < 4; i++)
#pragma unroll
                for (int j = 0; j < 4; j++)
                    acc[i][j] += ra[i] * rb[j];
        }
    }

    float4 bb = make_float4(0.f, 0.f, 0.f, 0.f);
    if (bias) bb = *(const float4*)&bias[bn + (tx << 2)];
#pragma unroll
    for (int i = 0; i < 4; i++) {
        int row = bm + (ty << 2) + i;
        float4 o;
        o.x = acc[i][0] + bb.x;
        o.y = acc[i][1] + bb.y;
        o.z = acc[i][2] + bb.z;
        o.w = acc[i][3] + bb.w;
        *(float4*)&C[(size_t)row * N + bn + (tx << 2)] = o;
    }
}

// ---------------------------------------------------------------------------
// RoPE + scatter qkv[B,T, NH*3*HD] -> Q/K/V in [B,NH,T,HD] (q pre-scaled).
// One block per (b,t); 256 threads, 4 iterations cover NH*HD=1024 (h,d) pairs.
// ---------------------------------------------------------------------------
__global__ __launch_bounds__(256) void rope_kernel(
    const float* __restrict__ qkv,
    float* __restrict__ Q, float* __restrict__ K, float* __restrict__ V)
{
    const int bt = blockIdx.x;
    const int b = bt >> 11;           // / 2048
    const int t = bt & 2047;
    const float* row = qkv + (size_t)bt * (3 * HDIM);
    const float LN1E4_OVER_32 = 0.28782313662425575f;  // ln(10000)/32

#pragma unroll
    for (int it = 0; it < 4; it++) {
        int idx = it * 256 + threadIdx.x;   // 0..1023
        int h = idx >> 6;
        int d = idx & 63;
        const float* base = row + h * (3 * HD);
        float qv = base[d];
        float kv = base[HD + d];
        float vv = base[2 * HD + d];
        int fi = d & 31;
        float inv = expf(-(float)fi * LN1E4_OVER_32);
        float ang = (float)t * inv;
        float sv, cv;
        sincosf(ang, &sv, &cv);
        float qrot = (d < 32) ? -base[d + 32] : base[d - 32];
        float krot = (d < 32) ? -base[HD + d + 32] : base[HD + d - 32];
        size_t o = (((size_t)(b * NHEAD + h) * T_SEQ) + t) * HD + d;
        Q[o] = (qv * cv + qrot * sv) * 0.125f;   // 1/sqrt(64) folded in
        K[o] = kv * cv + krot * sv;
        V[o] = vv;
    }
}

// ---------------------------------------------------------------------------
// Flash attention, fp32. One block per (qblock, b*h). 64x64 tiles, 256 thr,
// 4x4 per-thread register tiles for both S=QK^T and O+=P V.
// Online softmax state (m, l, corr) per query row in shared.
// ---------------------------------------------------------------------------
#define QSTR 68   // stride for Qt/Kt/Vs (float4-aligned, padded)
#define SSTR 65   // stride for Ss (conflict-free scalar row scans)

__global__ __launch_bounds__(256) void attn_kernel(
    const float* __restrict__ Q, const float* __restrict__ K,
    const float* __restrict__ V, const int* __restrict__ amask,
    float* __restrict__ out)
{
    extern __shared__ float sm[];
    float* Qt = sm;                       // [64][QSTR], Qt[d][row]
    float* Kt = Qt + 64 * QSTR;           // [64][QSTR], Kt[d][col]
    float* Vs = Kt + 64 * QSTR;           // [64][QSTR], Vs[key][d]
    float* Ss = Vs + 64 * QSTR;           // [64][SSTR], Ss[row][key]
    float* row_m = Ss + 64 * SSTR;
    float* row_l = row_m + 64;
    float* row_c = row_l + 64;
    int* smask = (int*)(row_c + 64);

    const int tid = threadIdx.x;
    const int ty = tid >> 4, tx = tid & 15;
    const int qb = blockIdx.x;            // query block 0..31
    const int bh = blockIdx.y;            // 0..31
    const int b = bh >> 4;

    const float* Qb = Q + ((size_t)bh * T_SEQ + qb * 64) * HD;
    const float* Kbase = K + (size_t)bh * T_SEQ * HD;
    const float* Vbase = V + (size_t)bh * T_SEQ * HD;

    // Load Q tile transposed: Qt[d][row]
#pragma unroll
    for (int it = 0; it < 4; it++) {
        int idx = it * 256 + tid;
        int r = idx >> 4, d4 = (idx & 15) << 2;
        float4 v = *(const float4*)(Qb + r * HD + d4);
        Qt[(d4 + 0) * QSTR + r] = v.x;
        Qt[(d4 + 1) * QSTR + r] = v.y;
        Qt[(d4 + 2) * QSTR + r] = v.z;
        Qt[(d4 + 3) * QSTR + r] = v.w;
    }
    if (tid < 64) { row_m[tid] = -1e30f; row_l[tid] = 0.f; }

    float acc[4][4] = {};

    for (int jb = 0; jb <= qb; jb++) {
        __syncthreads();   // prev iteration done with Kt/Vs/Ss
        const float* Kb = Kbase + (size_t)jb * 64 * HD;
        const float* Vb = Vbase + (size_t)jb * 64 * HD;
#pragma unroll
        for (int it = 0; it < 4; it++) {
            int idx = it * 256 + tid;
            int r = idx >> 4, d4 = (idx & 15) << 2;
            float4 kv = *(const float4*)(Kb + r * HD + d4);
            Kt[(d4 + 0) * QSTR + r] = kv.x;
            Kt[(d4 + 1) * QSTR + r] = kv.y;
            Kt[(d4 + 2) * QSTR + r] = kv.z;
            Kt[(d4 + 3) * QSTR + r] = kv.w;
            float4 vv = *(const float4*)(Vb + r * HD + d4);
            *(float4*)&Vs[r * QSTR + d4] = vv;
        }
        if (tid < 64) smask[tid] = amask[b * T_SEQ + jb * 64 + tid];
        __syncthreads();

        // S = Q K^T (scale folded into Q)
        float s[4][4] = {};
#pragma unroll
        for (int d = 0; d < 64; d++) {
            float qa[4], kb[4];
            *(float4*)qa = *(const float4*)&Qt[d * QSTR + (ty << 2)];
            *(float4*)kb = *(const float4*)&Kt[d * QSTR + (tx << 2)];
#pragma unroll
            for (int i = 0; i < 4; i++)
#pragma unroll
                for (int j = 0; j < 4; j++)
                    s[i][j] += qa[i] * kb[j];
        }
        const bool diag = (jb == qb);
#pragma unroll
        for (int i = 0; i < 4; i++)
#pragma unroll
            for (int j = 0; j < 4; j++) {
                int qi = (ty << 2) + i, kj = (tx << 2) + j;
                bool valid = (smask[kj] != 0) && (!diag || kj <= qi);
                Ss[qi * SSTR + kj] = valid ? s[i][j] : -1e30f;
            }
        __syncthreads();

        // Online softmax per query row (64 rows, one thread each)
        if (tid < 64) {
            float m = row_m[tid], mx = m;
            float* srow = Ss + tid * SSTR;
#pragma unroll 8
            for (int k2 = 0; k2 < 64; k2++) mx = fmaxf(mx, srow[k2]);
            float corr = __expf(m - mx);
            float sum = 0.f;
#pragma unroll 8
            for (int k2 = 0; k2 < 64; k2++) {
                float p = __expf(srow[k2] - mx);
                srow[k2] = p;
                sum += p;
            }
            row_l[tid] = row_l[tid] * corr + sum;
            row_m[tid] = mx;
            row_c[tid] = corr;
        }
        __syncthreads();

        // Rescale accumulator and O += P @ V
        float c0 = row_c[(ty << 2) + 0];
        float c1 = row_c[(ty << 2) + 1];
        float c2 = row_c[(ty << 2) + 2];
        float c3 = row_c[(ty << 2) + 3];
#pragma unroll
        for (int j = 0; j < 4; j++) {
            acc[0][j] *= c0; acc[1][j] *= c1; acc[2][j] *= c2; acc[3][j] *= c3;
        }
#pragma unroll
        for (int k2 = 0; k2 < 64; k2++) {
            float vv[4];
            *(float4*)vv = *(const float4*)&Vs[k2 * QSTR + (tx << 2)];
            float p0 = Ss[((ty << 2) + 0) * SSTR + k2];
            float p1 = Ss[((ty << 2) + 1) * SSTR + k2];
            float p2 = Ss[((ty << 2) + 2) * SSTR + k2];
            float p3 = Ss[((ty << 2) + 3) * SSTR + k2];
#pragma unroll
            for (int j = 0; j < 4; j++) {
                acc[0][j] += p0 * vv[j];
                acc[1][j] += p1 * vv[j];
                acc[2][j] += p2 * vv[j];
                acc[3][j] += p3 * vv[j];
            }
        }
    }
    __syncthreads();

    const int h = bh & 15;
#pragma unroll
    for (int i = 0; i < 4; i++) {
        float inv = 1.0f / row_l[(ty << 2) + i];
        int row = b * T_SEQ + qb * 64 + (ty << 2) + i;
        float4 o;
        o.x = acc[i][0] * inv;
        o.y = acc[i][1] * inv;
        o.z = acc[i][2] * inv;
        o.w = acc[i][3] * inv;
        *(float4*)&out[(size_t)row * HDIM + h * HD + (tx << 2)] = o;
    }
}

// ---------------------------------------------------------------------------
// Launch
// ---------------------------------------------------------------------------
extern "C" void kernel_launch(void* const* d_in, const int* in_sizes, int n_in,
                              void* d_out, int out_size)
{
    const float* hidden = (const float*)d_in[0];
    const int*   amask  = (const int*)d_in[1];
    const float* w_qkv  = (const float*)d_in[2];
    const float* b_qkv  = (const float*)d_in[3];
    const float* w_out  = (const float*)d_in[4];
    float* out = (float*)d_out;

    float *qkv, *Q, *K, *V, *attn;
    cudaGetSymbolAddress((void**)&qkv,  g_qkv);
    cudaGetSymbolAddress((void**)&Q,    g_Q);
    cudaGetSymbolAddress((void**)&K,    g_K);
    cudaGetSymbolAddress((void**)&V,    g_V);
    cudaGetSymbolAddress((void**)&attn, g_attn);

    // Allow >48KB dynamic shared for attention (idempotent, capture-safe)
    const int attn_smem = (3 * 64 * QSTR + 64 * SSTR + 3 * 64) * 4 + 64 * 4;
    cudaFuncSetAttribute(attn_kernel, cudaFuncAttributeMaxDynamicSharedMemorySize,
                         attn_smem);

    // 1) qkv = hidden @ w_qkv + b_qkv   [4096,1024]x[1024,3072]
    sgemm_bias<<<dim3(3 * HDIM / BN, MROWS / BM), 256>>>(
        hidden, w_qkv, b_qkv, qkv, MROWS, 3 * HDIM, HDIM);

    // 2) RoPE + scatter to head-major Q/K/V (q pre-scaled by 1/8)
    rope_kernel<<<MROWS, 256>>>(qkv, Q, K, V);

    // 3) causal+padded flash attention -> attn [B,T,H]
    attn_kernel<<<dim3(T_SEQ / 64, BATCH * NHEAD), 256, attn_smem>>>(
        Q, K, V, amask, attn);

    // 4) out = attn @ w_out   [4096,1024]x[1024,1024]
    sgemm_bias<<<dim3(HDIM / BN, MROWS / BM), 256>>>(
        attn, w_out, nullptr, out, MROWS, HDIM, HDIM);
}

// round 3
// speedup vs baseline: 1.5688x; 1.5688x over previous
#include <cuda_runtime.h>
#include <cstdint>
#include <cstddef>

// Problem constants
#define T_SEQ  2048
#define NHEAD  16
#define HDIM   1024
#define HD     64
#define BATCH  2
#define MROWS  (BATCH * T_SEQ)   // 4096

// Scratch (device globals; no allocations allowed)
__device__ float g_qkv[MROWS * 3 * HDIM];
__device__ float g_Q[BATCH * NHEAD * T_SEQ * HD];
__device__ float g_K[BATCH * NHEAD * T_SEQ * HD];
__device__ float g_V[BATCH * NHEAD * T_SEQ * HD];
__device__ float g_attn[MROWS * HDIM];
__device__ float g_Ar[MROWS * HDIM];                 // tf32-rounded hidden
__device__ float g_Bt1[3 * HDIM * HDIM];             // w_qkv^T rounded [3072,1024]
__device__ float g_Bt2[HDIM * HDIM];                 // w_out^T rounded [1024,1024]

// ---------------------------------------------------------------------------
// Helpers
// ---------------------------------------------------------------------------
__device__ __forceinline__ float to_tf32(float x) {
    uint32_t u;
    asm("cvt.rna.tf32.f32 %0, %1;" : "=r"(u) : "f"(x));
    return __uint_as_float(u);
}

__device__ __forceinline__ void cp16(uint32_t dst, const void* src) {
    asm volatile("cp.async.cg.shared.global [%0], [%1], 16;\n" :: "r"(dst), "l"(src));
}
__device__ __forceinline__ void cp_commit() {
    asm volatile("cp.async.commit_group;\n");
}
__device__ __forceinline__ void cp_wait3() {
    asm volatile("cp.async.wait_group 3;\n");
}

__device__ __forceinline__ void mma_tf32(float* c, const uint32_t* a, const uint32_t* b) {
    asm volatile(
        "mma.sync.aligned.m16n8k8.row.col.f32.tf32.tf32.f32 "
        "{%0,%1,%2,%3}, {%4,%5,%6,%7}, {%8,%9}, {%0,%1,%2,%3};"
        : "+f"(c[0]), "+f"(c[1]), "+f"(c[2]), "+f"(c[3])
        : "r"(a[0]), "r"(a[1]), "r"(a[2]), "r"(a[3]), "r"(b[0]), "r"(b[1]));
}

// ---------------------------------------------------------------------------
// tf32 mma.sync GEMM: C[M,N] = A[M,K] @ Bt[N,K]^T (+bias)
// 128x128x16 CTA tile, 256 threads, 8 warps (2x4), warp tile 64x32.
// 4-stage cp.async pipeline. A/Bt must be tf32-pre-rounded.
// ---------------------------------------------------------------------------
#define ASTR 20                          // floats per smem row (16 + 4 pad)
#define STAGE_FLOATS (2 * 128 * ASTR)    // A tile then B tile
#define STAGE_BYTES (STAGE_FLOATS * 4)   // 20480
#define GEMM_SMEM (4 * STAGE_BYTES)      // 81920

__global__ __launch_bounds__(256) void tf32_mma_gemm(
    const float* __restrict__ A, const float* __restrict__ Bt,
    const float* __restrict__ bias, float* __restrict__ C,
    int N, int K)
{
    extern __shared__ __align__(128) float smf[];
    const uint32_t sbase = (uint32_t)__cvta_generic_to_shared(smf);

    const int tid = threadIdx.x, lane = tid & 31, w = tid >> 5;
    const int wm = w & 1, wn = w >> 1;           // warp 2x4 grid
    const int g = lane >> 2, tig = lane & 3;
    const int bm = blockIdx.y * 128, bn = blockIdx.x * 128;

    // Global load mapping: each thread copies 2 A-float4s + 2 B-float4s / stage
    const int lm0 = tid >> 2;            // 0..63
    const int lkq = (tid & 3) * 4;       // 0,4,8,12
    const float* Ag0 = A + (size_t)(bm + lm0) * K + lkq;
    const float* Ag1 = Ag0 + (size_t)64 * K;
    const float* Bg0 = Bt + (size_t)(bn + lm0) * K + lkq;
    const float* Bg1 = Bg0 + (size_t)64 * K;
    const uint32_t offA0 = (lm0 * ASTR + lkq) * 4;
    const uint32_t offA1 = ((lm0 + 64) * ASTR + lkq) * 4;
    const uint32_t offB0 = 128 * ASTR * 4 + offA0;
    const uint32_t offB1 = 128 * ASTR * 4 + offA1;

    const int nchunks = K / 16;

    // Prologue: fill 4 stages
#pragma unroll
    for (int s = 0; s < 4; s++) {
        uint32_t so = sbase + s * STAGE_BYTES;
        cp16(so + offA0, Ag0 + s * 16);
        cp16(so + offA1, Ag1 + s * 16);
        cp16(so + offB0, Bg0 + s * 16);
        cp16(so + offB1, Bg1 + s * 16);
        cp_commit();
    }

    float acc[4][4][4] = {};

    for (int c = 0; c < nchunks; c++) {
        cp_wait3();
        __syncthreads();

        const float* sm = smf + (c & 3) * STAGE_FLOATS;
        const float* sB = sm + 128 * ASTR;

#pragma unroll
        for (int ks = 0; ks < 16; ks += 8) {
            uint32_t afr[4][4];
#pragma unroll
            for (int i = 0; i < 4; i++) {
                const float* pr = sm + (wm * 64 + i * 16 + g) * ASTR + ks + tig;
                afr[i][0] = __float_as_uint(pr[0]);
                afr[i][1] = __float_as_uint(pr[8 * ASTR]);
                afr[i][2] = __float_as_uint(pr[4]);
                afr[i][3] = __float_as_uint(pr[8 * ASTR + 4]);
            }
            uint32_t bfr[4][2];
#pragma unroll
            for (int j = 0; j < 4; j++) {
                const float* pb = sB + (wn * 32 + j * 8 + g) * ASTR + ks + tig;
                bfr[j][0] = __float_as_uint(pb[0]);
                bfr[j][1] = __float_as_uint(pb[4]);
            }
#pragma unroll
            for (int i = 0; i < 4; i++)
#pragma unroll
                for (int j = 0; j < 4; j++)
                    mma_tf32(acc[i][j], afr[i], bfr[j]);
        }
        __syncthreads();

        if (c + 4 < nchunks) {
            uint32_t so = sbase + (c & 3) * STAGE_BYTES;
            const int k0 = (c + 4) * 16;
            cp16(so + offA0, Ag0 + k0);
            cp16(so + offA1, Ag1 + k0);
            cp16(so + offB0, Bg0 + k0);
            cp16(so + offB1, Bg1 + k0);
        }
        cp_commit();
    }

    // Epilogue
#pragma unroll
    for (int i = 0; i < 4; i++) {
        const int r0 = bm + wm * 64 + i * 16 + g;
#pragma unroll
        for (int j = 0; j < 4; j++) {
            const int c0 = bn + wn * 32 + j * 8 + tig * 2;
            float bx = 0.f, by = 0.f;
            if (bias) { bx = bias[c0]; by = bias[c0 + 1]; }
            float2 o0 = make_float2(acc[i][j][0] + bx, acc[i][j][1] + by);
            float2 o1 = make_float2(acc[i][j][2] + bx, acc[i][j][3] + by);
            *(float2*)&C[(size_t)r0 * N + c0] = o0;
            *(float2*)&C[(size_t)(r0 + 8) * N + c0] = o1;
        }
    }
}

// ---------------------------------------------------------------------------
// Prep: tf32-round copy, and transpose+round (src[K,N] -> dst[N,K])
// ---------------------------------------------------------------------------
__global__ __launch_bounds__(256) void round_tf32_kernel(
    const float* __restrict__ src, float* __restrict__ dst)
{
    int i = blockIdx.x * 256 + threadIdx.x;
    float4 v = ((const float4*)src)[i];
    v.x = to_tf32(v.x); v.y = to_tf32(v.y);
    v.z = to_tf32(v.z); v.w = to_tf32(v.w);
    ((float4*)dst)[i] = v;
}

__global__ __launch_bounds__(256) void transpose_round_kernel(
    const float* __restrict__ src, float* __restrict__ dst, int K, int N)
{
    __shared__ float t[32][33];
    int n0 = blockIdx.x * 32, k0 = blockIdx.y * 32;
    int x = threadIdx.x & 31, y = threadIdx.x >> 5;   // 32 x 8
#pragma unroll
    for (int i = 0; i < 4; i++)
        t[y + i * 8][x] = src[(size_t)(k0 + y + i * 8) * N + n0 + x];
    __syncthreads();
#pragma unroll
    for (int i = 0; i < 4; i++)
        dst[(size_t)(n0 + y + i * 8) * K + k0 + x] = to_tf32(t[x][y + i * 8]);
}

// ---------------------------------------------------------------------------
// RoPE + scatter qkv[B,T, NH*3*HD] -> Q/K/V in [B,NH,T,HD] (q pre-scaled).
// ---------------------------------------------------------------------------
__global__ __launch_bounds__(256) void rope_kernel(
    const float* __restrict__ qkv,
    float* __restrict__ Q, float* __restrict__ K, float* __restrict__ V)
{
    const int bt = blockIdx.x;
    const int b = bt >> 11;
    const int t = bt & 2047;
    const float* row = qkv + (size_t)bt * (3 * HDIM);
    const float LN1E4_OVER_32 = 0.28782313662425575f;  // ln(10000)/32

#pragma unroll
    for (int it = 0; it < 4; it++) {
        int idx = it * 256 + threadIdx.x;
        int h = idx >> 6;
        int d = idx & 63;
        const float* base = row + h * (3 * HD);
        float qv = base[d];
        float kv = base[HD + d];
        float vv = base[2 * HD + d];
        int fi = d & 31;
        float inv = expf(-(float)fi * LN1E4_OVER_32);
        float ang = (float)t * inv;
        float sv, cv;
        sincosf(ang, &sv, &cv);
        float qrot = (d < 32) ? -base[d + 32] : base[d - 32];
        float krot = (d < 32) ? -base[HD + d + 32] : base[HD + d - 32];
        size_t o = (((size_t)(b * NHEAD + h) * T_SEQ) + t) * HD + d;
        Q[o] = (qv * cv + qrot * sv) * 0.125f;
        K[o] = kv * cv + krot * sv;
        V[o] = vv;
    }
}

// ---------------------------------------------------------------------------
// Flash attention, fp32 (output tf32-rounded since it feeds the tf32 GEMM).
// ---------------------------------------------------------------------------
#define QSTR 68
#define SSTR 65

__global__ __launch_bounds__(256) void attn_kernel(
    const float* __restrict__ Q, const float* __restrict__ K,
    const float* __restrict__ V, const int* __restrict__ amask,
    float* __restrict__ out)
{
    extern __shared__ float smf2[];
    float* Qt = smf2;
    float* Kt = Qt + 64 * QSTR;
    float* Vs = Kt + 64 * QSTR;
    float* Ss = Vs + 64 * QSTR;
    float* row_m = Ss + 64 * SSTR;
    float* row_l = row_m + 64;
    float* row_c = row_l + 64;
    int* smask = (int*)(row_c + 64);

    const int tid = threadIdx.x;
    const int ty = tid >> 4, tx = tid & 15;
    const int qb = blockIdx.x;
    const int bh = blockIdx.y;
    const int b = bh >> 4;

    const float* Qb = Q + ((size_t)bh * T_SEQ + qb * 64) * HD;
    const float* Kbase = K + (size_t)bh * T_SEQ * HD;
    const float* Vbase = V + (size_t)bh * T_SEQ * HD;

#pragma unroll
    for (int it = 0; it < 4; it++) {
        int idx = it * 256 + tid;
        int r = idx >> 4, d4 = (idx & 15) << 2;
        float4 v = *(const float4*)(Qb + r * HD + d4);
        Qt[(d4 + 0) * QSTR + r] = v.x;
        Qt[(d4 + 1) * QSTR + r] = v.y;
        Qt[(d4 + 2) * QSTR + r] = v.z;
        Qt[(d4 + 3) * QSTR + r] = v.w;
    }
    if (tid < 64) { row_m[tid] = -1e30f; row_l[tid] = 0.f; }

    float acc[4][4] = {};

    for (int jb = 0; jb <= qb; jb++) {
        __syncthreads();
        const float* Kb = Kbase + (size_t)jb * 64 * HD;
        const float* Vb = Vbase + (size_t)jb * 64 * HD;
#pragma unroll
        for (int it = 0; it < 4; it++) {
            int idx = it * 256 + tid;
            int r = idx >> 4, d4 = (idx & 15) << 2;
            float4 kv = *(const float4*)(Kb + r * HD + d4);
            Kt[(d4 + 0) * QSTR + r] = kv.x;
            Kt[(d4 + 1) * QSTR + r] = kv.y;
            Kt[(d4 + 2) * QSTR + r] = kv.z;
            Kt[(d4 + 3) * QSTR + r] = kv.w;
            float4 vv = *(const float4*)(Vb + r * HD + d4);
            *(float4*)&Vs[r * QSTR + d4] = vv;
        }
        if (tid < 64) smask[tid] = amask[b * T_SEQ + jb * 64 + tid];
        __syncthreads();

        float s[4][4] = {};
#pragma unroll
        for (int d = 0; d < 64; d++) {
            float qa[4], kb[4];
            *(float4*)qa = *(const float4*)&Qt[d * QSTR + (ty << 2)];
            *(float4*)kb = *(const float4*)&Kt[d * QSTR + (tx << 2)];
#pragma unroll
            for (int i = 0; i < 4; i++)
#pragma unroll
                for (int j = 0; j < 4; j++)
                    s[i][j] += qa[i] * kb[j];
        }
        const bool diag = (jb == qb);
#pragma unroll
        for (int i = 0; i < 4; i++)
#pragma unroll
            for (int j = 0; j < 4; j++) {
                int qi = (ty << 2) + i, kj = (tx << 2) + j;
                bool valid = (smask[kj] != 0) && (!diag || kj <= qi);
                Ss[qi * SSTR + kj] = valid ? s[i][j] : -1e30f;
            }
        __syncthreads();

        if (tid < 64) {
            float m = row_m[tid], mx = m;
            float* srow = Ss + tid * SSTR;
#pragma unroll 8
            for (int k2 = 0; k2 < 64; k2++) mx = fmaxf(mx, srow[k2]);
            float corr = __expf(m - mx);
            float sum = 0.f;
#pragma unroll 8
            for (int k2 = 0; k2 < 64; k2++) {
                float p = __expf(srow[k2] - mx);
                srow[k2] = p;
                sum += p;
            }
            row_l[tid] = row_l[tid] * corr + sum;
            row_m[tid] = mx;
            row_c[tid] = corr;
        }
        __syncthreads();

        float c0 = row_c[(ty << 2) + 0];
        float c1 = row_c[(ty << 2) + 1];
        float c2 = row_c[(ty << 2) + 2];
        float c3 = row_c[(ty << 2) + 3];
#pragma unroll
        for (int j = 0; j < 4; j++) {
            acc[0][j] *= c0; acc[1][j] *= c1; acc[2][j] *= c2; acc[3][j] *= c3;
        }
#pragma unroll
        for (int k2 = 0; k2 < 64; k2++) {
            float vv[4];
            *(float4*)vv = *(const float4*)&Vs[k2 * QSTR + (tx << 2)];
            float p0 = Ss[((ty << 2) + 0) * SSTR + k2];
            float p1 = Ss[((ty << 2) + 1) * SSTR + k2];
            float p2 = Ss[((ty << 2) + 2) * SSTR + k2];
            float p3 = Ss[((ty << 2) + 3) * SSTR + k2];
#pragma unroll
            for (int j = 0; j < 4; j++) {
                acc[0][j] += p0 * vv[j];
                acc[1][j] += p1 * vv[j];
                acc[2][j] += p2 * vv[j];
                acc[3][j] += p3 * vv[j];
            }
        }
    }
    __syncthreads();

    const int h = bh & 15;
#pragma unroll
    for (int i = 0; i < 4; i++) {
        float inv = 1.0f / row_l[(ty << 2) + i];
        int row = b * T_SEQ + qb * 64 + (ty << 2) + i;
        float4 o;
        o.x = to_tf32(acc[i][0] * inv);
        o.y = to_tf32(acc[i][1] * inv);
        o.z = to_tf32(acc[i][2] * inv);
        o.w = to_tf32(acc[i][3] * inv);
        *(float4*)&out[(size_t)row * HDIM + h * HD + (tx << 2)] = o;
    }
}

// ---------------------------------------------------------------------------
// Launch
// ---------------------------------------------------------------------------
extern "C" void kernel_launch(void* const* d_in, const int* in_sizes, int n_in,
                              void* d_out, int out_size)
{
    const float* hidden = (const float*)d_in[0];
    const int*   amask  = (const int*)d_in[1];
    const float* w_qkv  = (const float*)d_in[2];
    const float* b_qkv  = (const float*)d_in[3];
    const float* w_out  = (const float*)d_in[4];
    float* out = (float*)d_out;

    float *qkv, *Q, *K, *V, *attn, *Ar, *Bt1, *Bt2;
    cudaGetSymbolAddress((void**)&qkv,  g_qkv);
    cudaGetSymbolAddress((void**)&Q,    g_Q);
    cudaGetSymbolAddress((void**)&K,    g_K);
    cudaGetSymbolAddress((void**)&V,    g_V);
    cudaGetSymbolAddress((void**)&attn, g_attn);
    cudaGetSymbolAddress((void**)&Ar,   g_Ar);
    cudaGetSymbolAddress((void**)&Bt1,  g_Bt1);
    cudaGetSymbolAddress((void**)&Bt2,  g_Bt2);

    const int attn_smem = (3 * 64 * QSTR + 64 * SSTR + 3 * 64) * 4 + 64 * 4;
    cudaFuncSetAttribute(attn_kernel, cudaFuncAttributeMaxDynamicSharedMemorySize,
                         attn_smem);
    cudaFuncSetAttribute(tf32_mma_gemm, cudaFuncAttributeMaxDynamicSharedMemorySize,
                         GEMM_SMEM);

    // 0) tf32-round A; transpose+round weights
    round_tf32_kernel<<<MROWS * HDIM / 4 / 256, 256>>>(hidden, Ar);
    transpose_round_kernel<<<dim3(3 * HDIM / 32, HDIM / 32), 256>>>(w_qkv, Bt1, HDIM, 3 * HDIM);
    transpose_round_kernel<<<dim3(HDIM / 32, HDIM / 32), 256>>>(w_out, Bt2, HDIM, HDIM);

    // 1) qkv = Ar @ w_qkv + b_qkv (tf32 mma.sync)
    tf32_mma_gemm<<<dim3(3 * HDIM / 128, MROWS / 128), 256, GEMM_SMEM>>>(
        Ar, Bt1, b_qkv, qkv, 3 * HDIM, HDIM);

    // 2) RoPE + scatter
    rope_kernel<<<MROWS, 256>>>(qkv, Q, K, V);

    // 3) flash attention (fp32, output tf32-rounded)
    attn_kernel<<<dim3(T_SEQ / 64, BATCH * NHEAD), 256, attn_smem>>>(
        Q, K, V, amask, attn);

    // 4) out = attn @ w_out (tf32 mma.sync)
    tf32_mma_gemm<<<dim3(HDIM / 128, MROWS / 128), 256, GEMM_SMEM>>>(
        attn, Bt2, nullptr, out, HDIM, HDIM);
}

// round 4
// speedup vs baseline: 2.5322x; 1.6142x over previous
#include <cuda_runtime.h>
#include <cstdint>
#include <cstddef>

// Problem constants
#define T_SEQ  2048
#define NHEAD  16
#define HDIM   1024
#define HD     64
#define BATCH  2
#define MROWS  (BATCH * T_SEQ)   // 4096

// Scratch (device globals; no allocations allowed)
__device__ float g_qkv[MROWS * 3 * HDIM];
__device__ float g_Q[BATCH * NHEAD * T_SEQ * HD];    // [bh][t][d], tf32, pre-scaled
__device__ float g_K[BATCH * NHEAD * T_SEQ * HD];    // [bh][t][d], tf32
__device__ float g_V[BATCH * NHEAD * T_SEQ * HD];    // [bh][d][t]  (TRANSPOSED), tf32
__device__ float g_attn[MROWS * HDIM];
__device__ float g_Ar[MROWS * HDIM];                 // tf32-rounded hidden
__device__ float g_Bt1[3 * HDIM * HDIM];             // w_qkv^T rounded [3072,1024]
__device__ float g_Bt2[HDIM * HDIM];                 // w_out^T rounded [1024,1024]

// ---------------------------------------------------------------------------
// Helpers
// ---------------------------------------------------------------------------
__device__ __forceinline__ float to_tf32(float x) {
    uint32_t u;
    asm("cvt.rna.tf32.f32 %0, %1;" : "=r"(u) : "f"(x));
    return __uint_as_float(u);
}

__device__ __forceinline__ void cp16(uint32_t dst, const void* src) {
    asm volatile("cp.async.cg.shared.global [%0], [%1], 16;\n" :: "r"(dst), "l"(src));
}
__device__ __forceinline__ void cp_commit() {
    asm volatile("cp.async.commit_group;\n");
}
__device__ __forceinline__ void cp_wait3() {
    asm volatile("cp.async.wait_group 3;\n");
}
__device__ __forceinline__ void cp_wait0() {
    asm volatile("cp.async.wait_group 0;\n");
}

__device__ __forceinline__ void mma_tf32(float* c, const uint32_t* a, const uint32_t* b) {
    asm volatile(
        "mma.sync.aligned.m16n8k8.row.col.f32.tf32.tf32.f32 "
        "{%0,%1,%2,%3}, {%4,%5,%6,%7}, {%8,%9}, {%0,%1,%2,%3};"
        : "+f"(c[0]), "+f"(c[1]), "+f"(c[2]), "+f"(c[3])
        : "r"(a[0]), "r"(a[1]), "r"(a[2]), "r"(a[3]), "r"(b[0]), "r"(b[1]));
}

// ---------------------------------------------------------------------------
// tf32 mma.sync GEMM: C[M,N] = A[M,K] @ Bt[N,K]^T (+bias)
// 128x128x16 CTA tile, 256 threads, 8 warps (2x4), warp tile 64x32.
// 4-stage cp.async pipeline. A/Bt must be tf32-pre-rounded.
// ---------------------------------------------------------------------------
#define ASTR 20                          // floats per smem row (16 + 4 pad)
#define STAGE_FLOATS (2 * 128 * ASTR)    // A tile then B tile
#define STAGE_BYTES (STAGE_FLOATS * 4)   // 20480
#define GEMM_SMEM (4 * STAGE_BYTES)      // 81920

__global__ __launch_bounds__(256) void tf32_mma_gemm(
    const float* __restrict__ A, const float* __restrict__ Bt,
    const float* __restrict__ bias, float* __restrict__ C,
    int N, int K)
{
    extern __shared__ __align__(128) float smf[];
    const uint32_t sbase = (uint32_t)__cvta_generic_to_shared(smf);

    const int tid = threadIdx.x, lane = tid & 31, w = tid >> 5;
    const int wm = w & 1, wn = w >> 1;           // warp 2x4 grid
    const int g = lane >> 2, tig = lane & 3;
    const int bm = blockIdx.y * 128, bn = blockIdx.x * 128;

    const int lm0 = tid >> 2;            // 0..63
    const int lkq = (tid & 3) * 4;       // 0,4,8,12
    const float* Ag0 = A + (size_t)(bm + lm0) * K + lkq;
    const float* Ag1 = Ag0 + (size_t)64 * K;
    const float* Bg0 = Bt + (size_t)(bn + lm0) * K + lkq;
    const float* Bg1 = Bg0 + (size_t)64 * K;
    const uint32_t offA0 = (lm0 * ASTR + lkq) * 4;
    const uint32_t offA1 = ((lm0 + 64) * ASTR + lkq) * 4;
    const uint32_t offB0 = 128 * ASTR * 4 + offA0;
    const uint32_t offB1 = 128 * ASTR * 4 + offA1;

    const int nchunks = K / 16;

#pragma unroll
    for (int s = 0; s < 4; s++) {
        uint32_t so = sbase + s * STAGE_BYTES;
        cp16(so + offA0, Ag0 + s * 16);
        cp16(so + offA1, Ag1 + s * 16);
        cp16(so + offB0, Bg0 + s * 16);
        cp16(so + offB1, Bg1 + s * 16);
        cp_commit();
    }

    float acc[4][4][4] = {};

    for (int c = 0; c < nchunks; c++) {
        cp_wait3();
        __syncthreads();

        const float* sm = smf + (c & 3) * STAGE_FLOATS;
        const float* sB = sm + 128 * ASTR;

#pragma unroll
        for (int ks = 0; ks < 16; ks += 8) {
            uint32_t afr[4][4];
#pragma unroll
            for (int i = 0; i < 4; i++) {
                const float* pr = sm + (wm * 64 + i * 16 + g) * ASTR + ks + tig;
                afr[i][0] = __float_as_uint(pr[0]);
                afr[i][1] = __float_as_uint(pr[8 * ASTR]);
                afr[i][2] = __float_as_uint(pr[4]);
                afr[i][3] = __float_as_uint(pr[8 * ASTR + 4]);
            }
            uint32_t bfr[4][2];
#pragma unroll
            for (int j = 0; j < 4; j++) {
                const float* pb = sB + (wn * 32 + j * 8 + g) * ASTR + ks + tig;
                bfr[j][0] = __float_as_uint(pb[0]);
                bfr[j][1] = __float_as_uint(pb[4]);
            }
#pragma unroll
            for (int i = 0; i < 4; i++)
#pragma unroll
                for (int j = 0; j < 4; j++)
                    mma_tf32(acc[i][j], afr[i], bfr[j]);
        }
        __syncthreads();

        if (c + 4 < nchunks) {
            uint32_t so = sbase + (c & 3) * STAGE_BYTES;
            const int k0 = (c + 4) * 16;
            cp16(so + offA0, Ag0 + k0);
            cp16(so + offA1, Ag1 + k0);
            cp16(so + offB0, Bg0 + k0);
            cp16(so + offB1, Bg1 + k0);
        }
        cp_commit();
    }

#pragma unroll
    for (int i = 0; i < 4; i++) {
        const int r0 = bm + wm * 64 + i * 16 + g;
#pragma unroll
        for (int j = 0; j < 4; j++) {
            const int c0 = bn + wn * 32 + j * 8 + tig * 2;
            float bx = 0.f, by = 0.f;
            if (bias) { bx = bias[c0]; by = bias[c0 + 1]; }
            float2 o0 = make_float2(acc[i][j][0] + bx, acc[i][j][1] + by);
            float2 o1 = make_float2(acc[i][j][2] + bx, acc[i][j][3] + by);
            *(float2*)&C[(size_t)r0 * N + c0] = o0;
            *(float2*)&C[(size_t)(r0 + 8) * N + c0] = o1;
        }
    }
}

// ---------------------------------------------------------------------------
// Prep: tf32-round copy, and transpose+round (src[K,N] -> dst[N,K])
// ---------------------------------------------------------------------------
__global__ __launch_bounds__(256) void round_tf32_kernel(
    const float* __restrict__ src, float* __restrict__ dst)
{
    int i = blockIdx.x * 256 + threadIdx.x;
    float4 v = ((const float4*)src)[i];
    v.x = to_tf32(v.x); v.y = to_tf32(v.y);
    v.z = to_tf32(v.z); v.w = to_tf32(v.w);
    ((float4*)dst)[i] = v;
}

__global__ __launch_bounds__(256) void transpose_round_kernel(
    const float* __restrict__ src, float* __restrict__ dst, int K, int N)
{
    __shared__ float t[32][33];
    int n0 = blockIdx.x * 32, k0 = blockIdx.y * 32;
    int x = threadIdx.x & 31, y = threadIdx.x >> 5;   // 32 x 8
#pragma unroll
    for (int i = 0; i < 4; i++)
        t[y + i * 8][x] = src[(size_t)(k0 + y + i * 8) * N + n0 + x];
    __syncthreads();
#pragma unroll
    for (int i = 0; i < 4; i++)
        dst[(size_t)(n0 + y + i * 8) * K + k0 + x] = to_tf32(t[x][y + i * 8]);
}

// ---------------------------------------------------------------------------
// RoPE + scatter qkv[B,T, NH*3*HD] -> Q/K [bh][t][d] and V^T [bh][d][t].
// All outputs tf32-rounded; Q pre-scaled by 1/8.
// ---------------------------------------------------------------------------
__global__ __launch_bounds__(256) void rope_kernel(
    const float* __restrict__ qkv,
    float* __restrict__ Q, float* __restrict__ K, float* __restrict__ Vt)
{
    const int bt = blockIdx.x;
    const int b = bt >> 11;
    const int t = bt & 2047;
    const float* row = qkv + (size_t)bt * (3 * HDIM);
    const float LN1E4_OVER_32 = 0.28782313662425575f;  // ln(10000)/32

#pragma unroll
    for (int it = 0; it < 4; it++) {
        int idx = it * 256 + threadIdx.x;
        int h = idx >> 6;
        int d = idx & 63;
        const float* base = row + h * (3 * HD);
        float qv = base[d];
        float kv = base[HD + d];
        float vv = base[2 * HD + d];
        int fi = d & 31;
        float inv = expf(-(float)fi * LN1E4_OVER_32);
        float ang = (float)t * inv;
        float sv, cv;
        sincosf(ang, &sv, &cv);
        float qrot = (d < 32) ? -base[d + 32] : base[d - 32];
        float krot = (d < 32) ? -base[HD + d + 32] : base[HD + d - 32];
        int bh = b * NHEAD + h;
        size_t o = ((size_t)bh * T_SEQ + t) * HD + d;
        Q[o] = to_tf32((qv * cv + qrot * sv) * 0.125f);
        K[o] = to_tf32(kv * cv + krot * sv);
        Vt[((size_t)bh * HD + d) * T_SEQ + t] = to_tf32(vv);
    }
}

// ---------------------------------------------------------------------------
// Flash attention with tf32 mma.sync.
// CTA: 128 queries x 64-key blocks, 256 threads (8 warps x 16 query rows).
// Q/K/Vt must be tf32-pre-rounded; Q pre-scaled. Output tf32-rounded.
// ---------------------------------------------------------------------------
#define AQS 72   // smem row stride (floats)
#define ATT_SMEM ((128 * AQS + 64 * AQS + 64 * AQS + 128 * AQS) * 4 + 64 * 4)

__global__ __launch_bounds__(256, 2) void attn_mma_kernel(
    const float* __restrict__ Q, const float* __restrict__ K,
    const float* __restrict__ Vt, const int* __restrict__ amask,
    float* __restrict__ out)
{
    extern __shared__ __align__(128) float s[];
    float* Qs  = s;                    // [128][AQS]
    float* Ks  = Qs + 128 * AQS;       // [64][AQS]
    float* Vts = Ks + 64 * AQS;        // [64][AQS]   Vts[d][key]
    float* Ps  = Vts + 64 * AQS;       // [128][AQS]
    int* smask = (int*)(Ps + 128 * AQS);

    const uint32_t sb = (uint32_t)__cvta_generic_to_shared(s);
    const uint32_t ksb = (uint32_t)__cvta_generic_to_shared(Ks);
    const uint32_t vsb = (uint32_t)__cvta_generic_to_shared(Vts);

    const int tid = threadIdx.x, lane = tid & 31, w = tid >> 5;
    const int g = lane >> 2, tig = lane & 3;
    const int qb = blockIdx.x;             // query block (128)
    const int bh = blockIdx.y;
    const int b = bh >> 4, h = bh & 15;

    // Load Q tile (128 x 64) once
    const float* Qg = Q + ((size_t)bh * T_SEQ + qb * 128) * HD;
#pragma unroll
    for (int it = 0; it < 8; it++) {
        int idx = it * 256 + tid;
        int r = idx >> 4, c4 = (idx & 15) << 2;
        cp16(sb + (r * AQS + c4) * 4, Qg + r * HD + c4);
    }
    cp_commit();

    float accO[8][4] = {};
    float m0 = -1e30f, m1 = -1e30f, l0 = 0.f, l1 = 0.f;

    const int qrow0 = qb * 128 + w * 16 + g;
    const int qrow1 = qrow0 + 8;
    const int nkb = 2 * qb + 2;

    for (int jb = 0; jb < nkb; jb++) {
        __syncthreads();   // previous iteration's compute done with Ks/Vts
        const float* Kg = K + ((size_t)bh * T_SEQ + jb * 64) * HD;
        const float* Vg = Vt + (size_t)bh * HD * T_SEQ + jb * 64;
#pragma unroll
        for (int it = 0; it < 4; it++) {
            int idx = it * 256 + tid;
            int r = idx >> 4, c4 = (idx & 15) << 2;
            cp16(ksb + (r * AQS + c4) * 4, Kg + r * HD + c4);
            cp16(vsb + (r * AQS + c4) * 4, Vg + (size_t)r * T_SEQ + c4);
        }
        if (tid < 64) smask[tid] = amask[b * T_SEQ + jb * 64 + tid];
        cp_commit();
        cp_wait0();
        __syncthreads();

        // ---- S = Q_tile @ K_tile^T ----
        uint32_t af[8][4];
        const float* qrow = Qs + (w * 16 + g) * AQS;
#pragma unroll
        for (int ks = 0; ks < 8; ks++) {
            af[ks][0] = __float_as_uint(qrow[ks * 8 + tig]);
            af[ks][1] = __float_as_uint(qrow[8 * AQS + ks * 8 + tig]);
            af[ks][2] = __float_as_uint(qrow[ks * 8 + tig + 4]);
            af[ks][3] = __float_as_uint(qrow[8 * AQS + ks * 8 + tig + 4]);
        }
        float sacc[8][4];
#pragma unroll
        for (int j = 0; j < 8; j++) {
            sacc[j][0] = sacc[j][1] = sacc[j][2] = sacc[j][3] = 0.f;
#pragma unroll
            for (int ks = 0; ks < 8; ks++) {
                uint32_t bf[2];
                const float* kb = Ks + (j * 8 + g) * AQS + ks * 8 + tig;
                bf[0] = __float_as_uint(kb[0]);
                bf[1] = __float_as_uint(kb[4]);
                mma_tf32(sacc[j], af[ks], bf);
            }
        }

        // ---- mask + online softmax ----
        float mx0 = m0, mx1 = m1;
#pragma unroll
        for (int j = 0; j < 8; j++) {
            int c = j * 8 + 2 * tig;
            int colg = jb * 64 + c;
            bool v0 = smask[c]     && (colg     <= qrow0);
            bool v1 = smask[c + 1] && (colg + 1 <= qrow0);
            bool v2 = smask[c]     && (colg     <= qrow1);
            bool v3 = smask[c + 1] && (colg + 1 <= qrow1);
            sacc[j][0] = v0 ? sacc[j][0] : -1e30f;
            sacc[j][1] = v1 ? sacc[j][1] : -1e30f;
            sacc[j][2] = v2 ? sacc[j][2] : -1e30f;
            sacc[j][3] = v3 ? sacc[j][3] : -1e30f;
            mx0 = fmaxf(mx0, fmaxf(sacc[j][0], sacc[j][1]));
            mx1 = fmaxf(mx1, fmaxf(sacc[j][2], sacc[j][3]));
        }
        mx0 = fmaxf(mx0, __shfl_xor_sync(0xffffffff, mx0, 1));
        mx0 = fmaxf(mx0, __shfl_xor_sync(0xffffffff, mx0, 2));
        mx1 = fmaxf(mx1, __shfl_xor_sync(0xffffffff, mx1, 1));
        mx1 = fmaxf(mx1, __shfl_xor_sync(0xffffffff, mx1, 2));
        float corr0 = __expf(m0 - mx0);
        float corr1 = __expf(m1 - mx1);
        m0 = mx0; m1 = mx1;

        float sum0 = 0.f, sum1 = 0.f;
        float* prow0 = Ps + (w * 16 + g) * AQS;
        float* prow1 = prow0 + 8 * AQS;
#pragma unroll
        for (int j = 0; j < 8; j++) {
            int c = j * 8 + 2 * tig;
            float p0 = to_tf32(__expf(sacc[j][0] - mx0));
            float p1 = to_tf32(__expf(sacc[j][1] - mx0));
            float p2 = to_tf32(__expf(sacc[j][2] - mx1));
            float p3 = to_tf32(__expf(sacc[j][3] - mx1));
            sum0 += p0 + p1;
            sum1 += p2 + p3;
            *(float2*)&prow0[c] = make_float2(p0, p1);
            *(float2*)&prow1[c] = make_float2(p2, p3);
        }
        sum0 += __shfl_xor_sync(0xffffffff, sum0, 1);
        sum0 += __shfl_xor_sync(0xffffffff, sum0, 2);
        sum1 += __shfl_xor_sync(0xffffffff, sum1, 1);
        sum1 += __shfl_xor_sync(0xffffffff, sum1, 2);
        l0 = l0 * corr0 + sum0;
        l1 = l1 * corr1 + sum1;

#pragma unroll
        for (int j = 0; j < 8; j++) {
            accO[j][0] *= corr0; accO[j][1] *= corr0;
            accO[j][2] *= corr1; accO[j][3] *= corr1;
        }
        __syncwarp();

        // ---- O += P @ V  (B operand from Vts[d][key]) ----
#pragma unroll
        for (int ks = 0; ks < 8; ks++) {
            uint32_t pa[4];
            const float* pp = Ps + (w * 16 + g) * AQS + ks * 8 + tig;
            pa[0] = __float_as_uint(pp[0]);
            pa[1] = __float_as_uint(pp[8 * AQS]);
            pa[2] = __float_as_uint(pp[4]);
            pa[3] = __float_as_uint(pp[8 * AQS + 4]);
#pragma unroll
            for (int j = 0; j < 8; j++) {
                uint32_t bf[2];
                const float* vb = Vts + (j * 8 + g) * AQS + ks * 8 + tig;
                bf[0] = __float_as_uint(vb[0]);
                bf[1] = __float_as_uint(vb[4]);
                mma_tf32(accO[j], pa, bf);
            }
        }
    }

    // ---- epilogue ----
    float inv0 = 1.f / l0, inv1 = 1.f / l1;
    const int r0 = b * T_SEQ + qb * 128 + w * 16 + g;
#pragma unroll
    for (int j = 0; j < 8; j++) {
        int c = h * HD + j * 8 + 2 * tig;
        float2 o0 = make_float2(to_tf32(accO[j][0] * inv0), to_tf32(accO[j][1] * inv0));
        float2 o1 = make_float2(to_tf32(accO[j][2] * inv1), to_tf32(accO[j][3] * inv1));
        *(float2*)&out[(size_t)r0 * HDIM + c] = o0;
        *(float2*)&out[(size_t)(r0 + 8) * HDIM + c] = o1;
    }
}

// ---------------------------------------------------------------------------
// Launch
// ---------------------------------------------------------------------------
extern "C" void kernel_launch(void* const* d_in, const int* in_sizes, int n_in,
                              void* d_out, int out_size)
{
    const float* hidden = (const float*)d_in[0];
    const int*   amask  = (const int*)d_in[1];
    const float* w_qkv  = (const float*)d_in[2];
    const float* b_qkv  = (const float*)d_in[3];
    const float* w_out  = (const float*)d_in[4];
    float* out = (float*)d_out;

    float *qkv, *Q, *K, *V, *attn, *Ar, *Bt1, *Bt2;
    cudaGetSymbolAddress((void**)&qkv,  g_qkv);
    cudaGetSymbolAddress((void**)&Q,    g_Q);
    cudaGetSymbolAddress((void**)&K,    g_K);
    cudaGetSymbolAddress((void**)&V,    g_V);
    cudaGetSymbolAddress((void**)&attn, g_attn);
    cudaGetSymbolAddress((void**)&Ar,   g_Ar);
    cudaGetSymbolAddress((void**)&Bt1,  g_Bt1);
    cudaGetSymbolAddress((void**)&Bt2,  g_Bt2);

    cudaFuncSetAttribute(attn_mma_kernel, cudaFuncAttributeMaxDynamicSharedMemorySize,
                         ATT_SMEM);
    cudaFuncSetAttribute(tf32_mma_gemm, cudaFuncAttributeMaxDynamicSharedMemorySize,
                         GEMM_SMEM);

    // 0) tf32-round A; transpose+round weights
    round_tf32_kernel<<<MROWS * HDIM / 4 / 256, 256>>>(hidden, Ar);
    transpose_round_kernel<<<dim3(3 * HDIM / 32, HDIM / 32), 256>>>(w_qkv, Bt1, HDIM, 3 * HDIM);
    transpose_round_kernel<<<dim3(HDIM / 32, HDIM / 32), 256>>>(w_out, Bt2, HDIM, HDIM);

    // 1) qkv = Ar @ w_qkv + b_qkv (tf32 mma.sync)
    tf32_mma_gemm<<<dim3(3 * HDIM / 128, MROWS / 128), 256, GEMM_SMEM>>>(
        Ar, Bt1, b_qkv, qkv, 3 * HDIM, HDIM);

    // 2) RoPE + scatter (Q/K rounded; V transposed+rounded)
    rope_kernel<<<MROWS, 256>>>(qkv, Q, K, V);

    // 3) tf32 mma flash attention -> attn [B,T,H] (tf32-rounded)
    attn_mma_kernel<<<dim3(T_SEQ / 128, BATCH * NHEAD), 256, ATT_SMEM>>>(
        Q, K, V, amask, attn);

    // 4) out = attn @ w_out (tf32 mma.sync)
    tf32_mma_gemm<<<dim3(HDIM / 128, MROWS / 128), 256, GEMM_SMEM>>>(
        attn, Bt2, nullptr, out, HDIM, HDIM);
}

// round 5
// speedup vs baseline: 3.4621x; 1.3672x over previous
#include <cuda_runtime.h>
#include <cstdint>
#include <cstddef>

// Problem constants
#define T_SEQ  2048
#define NHEAD  16
#define HDIM   1024
#define HD     64
#define BATCH  2
#define MROWS  (BATCH * T_SEQ)   // 4096

// Scratch (device globals; no allocations allowed)
__device__ float g_qkv[MROWS * 3 * HDIM];
__device__ float g_Q[BATCH * NHEAD * T_SEQ * HD];    // [bh][t][d], tf32, pre-scaled
__device__ float g_K[BATCH * NHEAD * T_SEQ * HD];    // [bh][t][d], tf32
__device__ float g_V[BATCH * NHEAD * T_SEQ * HD];    // [bh][d][t]  (TRANSPOSED), tf32
__device__ float g_attn[MROWS * HDIM];
__device__ float g_Ar[MROWS * HDIM];                 // tf32-rounded hidden
__device__ float g_Bt1[3 * HDIM * HDIM];             // w_qkv^T rounded [3072,1024]
__device__ float g_Bt2[HDIM * HDIM];                 // w_out^T rounded [1024,1024]

// ---------------------------------------------------------------------------
// Helpers
// ---------------------------------------------------------------------------
__device__ __forceinline__ float to_tf32(float x) {
    uint32_t u;
    asm("cvt.rna.tf32.f32 %0, %1;" : "=r"(u) : "f"(x));
    return __uint_as_float(u);
}

__device__ __forceinline__ void cp16(uint32_t dst, const void* src) {
    asm volatile("cp.async.cg.shared.global [%0], [%1], 16;\n" :: "r"(dst), "l"(src));
}
__device__ __forceinline__ void cp_commit() {
    asm volatile("cp.async.commit_group;\n");
}
__device__ __forceinline__ void cp_wait3() {
    asm volatile("cp.async.wait_group 3;\n");
}
__device__ __forceinline__ void cp_wait0() {
    asm volatile("cp.async.wait_group 0;\n");
}

__device__ __forceinline__ void mma_tf32(float* c, const uint32_t* a, const uint32_t* b) {
    asm volatile(
        "mma.sync.aligned.m16n8k8.row.col.f32.tf32.tf32.f32 "
        "{%0,%1,%2,%3}, {%4,%5,%6,%7}, {%8,%9}, {%0,%1,%2,%3};"
        : "+f"(c[0]), "+f"(c[1]), "+f"(c[2]), "+f"(c[3])
        : "r"(a[0]), "r"(a[1]), "r"(a[2]), "r"(a[3]), "r"(b[0]), "r"(b[1]));
}

__device__ __forceinline__ void ldsm4(uint32_t* r, uint32_t addr) {
    asm volatile("ldmatrix.sync.aligned.m8n8.x4.shared.b16 {%0,%1,%2,%3}, [%4];"
        : "=r"(r[0]), "=r"(r[1]), "=r"(r[2]), "=r"(r[3]) : "r"(addr));
}

// ---------------------------------------------------------------------------
// tf32 mma.sync GEMM with ldmatrix: C[M,N] = A[M,K] @ Bt[N,K]^T (+bias)
// 128x128x16 CTA tile, 256 threads, 8 warps (2x4), warp tile 64x32.
// 4-stage cp.async pipeline. A/Bt must be tf32-pre-rounded.
// ---------------------------------------------------------------------------
#define ASTR 20                          // floats per smem row (16 + 4 pad)
#define STAGE_FLOATS (2 * 128 * ASTR)    // A tile then B tile
#define STAGE_BYTES (STAGE_FLOATS * 4)   // 20480
#define GEMM_SMEM (4 * STAGE_BYTES)      // 81920

__global__ __launch_bounds__(256) void tf32_mma_gemm(
    const float* __restrict__ A, const float* __restrict__ Bt,
    const float* __restrict__ bias, float* __restrict__ C,
    int N, int K)
{
    extern __shared__ __align__(128) float smf[];
    const uint32_t sbase = (uint32_t)__cvta_generic_to_shared(smf);

    const int tid = threadIdx.x, lane = tid & 31, w = tid >> 5;
    const int wm = w & 1, wn = w >> 1;           // warp 2x4 grid
    const int g = lane >> 2, tig = lane & 3;
    const int bm = blockIdx.y * 128, bn = blockIdx.x * 128;

    // cp.async mapping
    const int lm0 = tid >> 2;            // 0..63
    const int lkq = (tid & 3) * 4;       // 0,4,8,12
    const float* Ag0 = A + (size_t)(bm + lm0) * K + lkq;
    const float* Ag1 = Ag0 + (size_t)64 * K;
    const float* Bg0 = Bt + (size_t)(bn + lm0) * K + lkq;
    const float* Bg1 = Bg0 + (size_t)64 * K;
    const uint32_t offA0 = (lm0 * ASTR + lkq) * 4;
    const uint32_t offA1 = ((lm0 + 64) * ASTR + lkq) * 4;
    const uint32_t offB0 = 128 * ASTR * 4 + offA0;
    const uint32_t offB1 = 128 * ASTR * 4 + offA1;

    // ldmatrix per-lane offsets
    // A x4 tiles: m0=(rows,k) m1=(rows+8,k) m2=(rows,k+4) m3=(rows+8,k+4)
    const uint32_t a_lrow = (lane & 7) + ((lane >> 3) & 1) * 8;
    const uint32_t a_lk = (lane >> 4) * 4;
    // B x4 tiles: m0=(n,k) m1=(n,k+4) m2=(n+8,k) m3=(n+8,k+4)
    const uint32_t b_lrow = (lane & 7) + ((lane >> 4) & 1) * 8;
    const uint32_t b_lk = ((lane >> 3) & 1) * 4;

    const uint32_t aAddr0 = sbase + ((wm * 64 + a_lrow) * ASTR + a_lk) * 4;
    const uint32_t bAddr0 = sbase + (128 * ASTR + (wn * 32 + b_lrow) * ASTR + b_lk) * 4;

    const int nchunks = K / 16;

#pragma unroll
    for (int s = 0; s < 4; s++) {
        uint32_t so = sbase + s * STAGE_BYTES;
        cp16(so + offA0, Ag0 + s * 16);
        cp16(so + offA1, Ag1 + s * 16);
        cp16(so + offB0, Bg0 + s * 16);
        cp16(so + offB1, Bg1 + s * 16);
        cp_commit();
    }

    float acc[4][4][4] = {};

    for (int c = 0; c < nchunks; c++) {
        cp_wait3();
        __syncthreads();

        const uint32_t st = (c & 3) * STAGE_BYTES;

#pragma unroll
        for (int ks = 0; ks < 16; ks += 8) {
            uint32_t afr[4][4];
#pragma unroll
            for (int i = 0; i < 4; i++)
                ldsm4(afr[i], aAddr0 + st + (i * 16 * ASTR + ks) * 4);
            uint32_t bfr[2][4];
#pragma unroll
            for (int jp = 0; jp < 2; jp++)
                ldsm4(bfr[jp], bAddr0 + st + (jp * 16 * ASTR + ks) * 4);
#pragma unroll
            for (int i = 0; i < 4; i++)
#pragma unroll
                for (int jp = 0; jp < 2; jp++) {
                    mma_tf32(acc[i][jp * 2],     afr[i], bfr[jp]);
                    mma_tf32(acc[i][jp * 2 + 1], afr[i], bfr[jp] + 2);
                }
        }
        __syncthreads();

        if (c + 4 < nchunks) {
            uint32_t so = sbase + (c & 3) * STAGE_BYTES;
            const int k0 = (c + 4) * 16;
            cp16(so + offA0, Ag0 + k0);
            cp16(so + offA1, Ag1 + k0);
            cp16(so + offB0, Bg0 + k0);
            cp16(so + offB1, Bg1 + k0);
        }
        cp_commit();
    }

#pragma unroll
    for (int i = 0; i < 4; i++) {
        const int r0 = bm + wm * 64 + i * 16 + g;
#pragma unroll
        for (int j = 0; j < 4; j++) {
            const int c0 = bn + wn * 32 + j * 8 + tig * 2;
            float bx = 0.f, by = 0.f;
            if (bias) { bx = bias[c0]; by = bias[c0 + 1]; }
            float2 o0 = make_float2(acc[i][j][0] + bx, acc[i][j][1] + by);
            float2 o1 = make_float2(acc[i][j][2] + bx, acc[i][j][3] + by);
            *(float2*)&C[(size_t)r0 * N + c0] = o0;
            *(float2*)&C[(size_t)(r0 + 8) * N + c0] = o1;
        }
    }
}

// ---------------------------------------------------------------------------
// Prep: tf32-round copy, and transpose+round (src[K,N] -> dst[N,K])
// ---------------------------------------------------------------------------
__global__ __launch_bounds__(256) void round_tf32_kernel(
    const float* __restrict__ src, float* __restrict__ dst)
{
    int i = blockIdx.x * 256 + threadIdx.x;
    float4 v = ((const float4*)src)[i];
    v.x = to_tf32(v.x); v.y = to_tf32(v.y);
    v.z = to_tf32(v.z); v.w = to_tf32(v.w);
    ((float4*)dst)[i] = v;
}

__global__ __launch_bounds__(256) void transpose_round_kernel(
    const float* __restrict__ src, float* __restrict__ dst, int K, int N)
{
    __shared__ float t[32][33];
    int n0 = blockIdx.x * 32, k0 = blockIdx.y * 32;
    int x = threadIdx.x & 31, y = threadIdx.x >> 5;   // 32 x 8
#pragma unroll
    for (int i = 0; i < 4; i++)
        t[y + i * 8][x] = src[(size_t)(k0 + y + i * 8) * N + n0 + x];
    __syncthreads();
#pragma unroll
    for (int i = 0; i < 4; i++)
        dst[(size_t)(n0 + y + i * 8) * K + k0 + x] = to_tf32(t[x][y + i * 8]);
}

// ---------------------------------------------------------------------------
// RoPE (Q/K only, coalesced) + separate tiled V transpose.
// ---------------------------------------------------------------------------
__global__ __launch_bounds__(256) void rope_kernel(
    const float* __restrict__ qkv,
    float* __restrict__ Q, float* __restrict__ K)
{
    const int bt = blockIdx.x;
    const int b = bt >> 11;
    const int t = bt & 2047;
    const float* row = qkv + (size_t)bt * (3 * HDIM);
    const float LN1E4_OVER_32 = 0.28782313662425575f;  // ln(10000)/32

#pragma unroll
    for (int it = 0; it < 4; it++) {
        int idx = it * 256 + threadIdx.x;
        int h = idx >> 6;
        int d = idx & 63;
        const float* base = row + h * (3 * HD);
        float qv = base[d];
        float kv = base[HD + d];
        int fi = d & 31;
        float inv = expf(-(float)fi * LN1E4_OVER_32);
        float ang = (float)t * inv;
        float sv, cv;
        sincosf(ang, &sv, &cv);
        float qrot = (d < 32) ? -base[d + 32] : base[d - 32];
        float krot = (d < 32) ? -base[HD + d + 32] : base[HD + d - 32];
        int bh = b * NHEAD + h;
        size_t o = ((size_t)bh * T_SEQ + t) * HD + d;
        Q[o] = to_tf32((qv * cv + qrot * sv) * 0.125f);
        K[o] = to_tf32(kv * cv + krot * sv);
    }
}

// V slice of qkv -> Vt [bh][d][t], tf32-rounded, tiled transpose.
__global__ __launch_bounds__(256) void vtrans_kernel(
    const float* __restrict__ qkv, float* __restrict__ Vt)
{
    __shared__ float t[32][33];
    const int t0 = blockIdx.x * 32;
    const int d0 = blockIdx.y * 32;
    const int bh = blockIdx.z;
    const int b = bh >> 4, h = bh & 15;
    const int x = threadIdx.x & 31, y = threadIdx.x >> 5;

#pragma unroll
    for (int i = 0; i < 4; i++)
        t[y + i * 8][x] =
            qkv[(size_t)(b * T_SEQ + t0 + y + i * 8) * (3 * HDIM) + h * 192 + 128 + d0 + x];
    __syncthreads();
#pragma unroll
    for (int i = 0; i < 4; i++)
        Vt[((size_t)bh * HD + d0 + y + i * 8) * T_SEQ + t0 + x] = to_tf32(t[x][y + i * 8]);
}

// ---------------------------------------------------------------------------
// Flash attention with tf32 mma.sync + ldmatrix.
// CTA: 128 queries x 64-key blocks, 256 threads (8 warps x 16 query rows).
// ---------------------------------------------------------------------------
#define AQS 68   // smem row stride (floats): 64 + 4; conflict-free for ldmatrix
#define ATT_SMEM ((128 * AQS + 64 * AQS + 64 * AQS + 128 * AQS) * 4 + 64 * 4)

__global__ __launch_bounds__(256, 2) void attn_mma_kernel(
    const float* __restrict__ Q, const float* __restrict__ K,
    const float* __restrict__ Vt, const int* __restrict__ amask,
    float* __restrict__ out)
{
    extern __shared__ __align__(128) float s[];
    float* Qs  = s;                    // [128][AQS]
    float* Ks  = Qs + 128 * AQS;       // [64][AQS]   Ks[key][d]
    float* Vts = Ks + 64 * AQS;        // [64][AQS]   Vts[d][key]
    float* Ps  = Vts + 64 * AQS;       // [128][AQS]
    int* smask = (int*)(Ps + 128 * AQS);

    const uint32_t sb  = (uint32_t)__cvta_generic_to_shared(s);
    const uint32_t ksb = (uint32_t)__cvta_generic_to_shared(Ks);
    const uint32_t vsb = (uint32_t)__cvta_generic_to_shared(Vts);
    const uint32_t psb = (uint32_t)__cvta_generic_to_shared(Ps);

    const int tid = threadIdx.x, lane = tid & 31, w = tid >> 5;
    const int g = lane >> 2, tig = lane & 3;
    const int qb = blockIdx.x;
    const int bh = blockIdx.y;
    const int b = bh >> 4, h = bh & 15;

    // ldmatrix per-lane offsets
    const uint32_t a_lrow = (lane & 7) + ((lane >> 3) & 1) * 8;
    const uint32_t a_lk = (lane >> 4) * 4;
    const uint32_t b_lrow = (lane & 7) + ((lane >> 4) & 1) * 8;
    const uint32_t b_lk = ((lane >> 3) & 1) * 4;

    const uint32_t qAddr0 = sb  + ((w * 16 + a_lrow) * AQS + a_lk) * 4;
    const uint32_t pAddr0 = psb + ((w * 16 + a_lrow) * AQS + a_lk) * 4;
    const uint32_t kAddr0 = ksb + (b_lrow * AQS + b_lk) * 4;
    const uint32_t vAddr0 = vsb + (b_lrow * AQS + b_lk) * 4;

    // Load Q tile (128 x 64) once
    const float* Qg = Q + ((size_t)bh * T_SEQ + qb * 128) * HD;
#pragma unroll
    for (int it = 0; it < 8; it++) {
        int idx = it * 256 + tid;
        int r = idx >> 4, c4 = (idx & 15) << 2;
        cp16(sb + (r * AQS + c4) * 4, Qg + r * HD + c4);
    }
    cp_commit();

    float accO[8][4] = {};
    float m0 = -1e30f, m1 = -1e30f, l0 = 0.f, l1 = 0.f;

    const int qrow0 = qb * 128 + w * 16 + g;
    const int qrow1 = qrow0 + 8;
    const int nkb = 2 * qb + 2;

    for (int jb = 0; jb < nkb; jb++) {
        __syncthreads();
        const float* Kg = K + ((size_t)bh * T_SEQ + jb * 64) * HD;
        const float* Vg = Vt + (size_t)bh * HD * T_SEQ + jb * 64;
#pragma unroll
        for (int it = 0; it < 4; it++) {
            int idx = it * 256 + tid;
            int r = idx >> 4, c4 = (idx & 15) << 2;
            cp16(ksb + (r * AQS + c4) * 4, Kg + r * HD + c4);
            cp16(vsb + (r * AQS + c4) * 4, Vg + (size_t)r * T_SEQ + c4);
        }
        if (tid < 64) smask[tid] = amask[b * T_SEQ + jb * 64 + tid];
        cp_commit();
        cp_wait0();
        __syncthreads();

        // ---- S = Q_tile @ K_tile^T ----
        float sacc[8][4];
#pragma unroll
        for (int j = 0; j < 8; j++)
            sacc[j][0] = sacc[j][1] = sacc[j][2] = sacc[j][3] = 0.f;
#pragma unroll
        for (int ks = 0; ks < 8; ks++) {
            uint32_t af[4];
            ldsm4(af, qAddr0 + ks * 32);
#pragma unroll
            for (int jp = 0; jp < 4; jp++) {
                uint32_t bf[4];
                ldsm4(bf, kAddr0 + (jp * 16 * AQS + ks * 8) * 4);
                mma_tf32(sacc[jp * 2],     af, bf);
                mma_tf32(sacc[jp * 2 + 1], af, bf + 2);
            }
        }

        // ---- mask + online softmax ----
        float mx0 = m0, mx1 = m1;
#pragma unroll
        for (int j = 0; j < 8; j++) {
            int c = j * 8 + 2 * tig;
            int colg = jb * 64 + c;
            bool v0 = smask[c]     && (colg     <= qrow0);
            bool v1 = smask[c + 1] && (colg + 1 <= qrow0);
            bool v2 = smask[c]     && (colg     <= qrow1);
            bool v3 = smask[c + 1] && (colg + 1 <= qrow1);
            sacc[j][0] = v0 ? sacc[j][0] : -1e30f;
            sacc[j][1] = v1 ? sacc[j][1] : -1e30f;
            sacc[j][2] = v2 ? sacc[j][2] : -1e30f;
            sacc[j][3] = v3 ? sacc[j][3] : -1e30f;
            mx0 = fmaxf(mx0, fmaxf(sacc[j][0], sacc[j][1]));
            mx1 = fmaxf(mx1, fmaxf(sacc[j][2], sacc[j][3]));
        }
        mx0 = fmaxf(mx0, __shfl_xor_sync(0xffffffff, mx0, 1));
        mx0 = fmaxf(mx0, __shfl_xor_sync(0xffffffff, mx0, 2));
        mx1 = fmaxf(mx1, __shfl_xor_sync(0xffffffff, mx1, 1));
        mx1 = fmaxf(mx1, __shfl_xor_sync(0xffffffff, mx1, 2));
        float corr0 = __expf(m0 - mx0);
        float corr1 = __expf(m1 - mx1);
        m0 = mx0; m1 = mx1;

        float sum0 = 0.f, sum1 = 0.f;
        float* prow0 = Ps + (w * 16 + g) * AQS;
        float* prow1 = prow0 + 8 * AQS;
#pragma unroll
        for (int j = 0; j < 8; j++) {
            int c = j * 8 + 2 * tig;
            float p0 = to_tf32(__expf(sacc[j][0] - mx0));
            float p1 = to_tf32(__expf(sacc[j][1] - mx0));
            float p2 = to_tf32(__expf(sacc[j][2] - mx1));
            float p3 = to_tf32(__expf(sacc[j][3] - mx1));
            sum0 += p0 + p1;
            sum1 += p2 + p3;
            *(float2*)&prow0[c] = make_float2(p0, p1);
            *(float2*)&prow1[c] = make_float2(p2, p3);
        }
        sum0 += __shfl_xor_sync(0xffffffff, sum0, 1);
        sum0 += __shfl_xor_sync(0xffffffff, sum0, 2);
        sum1 += __shfl_xor_sync(0xffffffff, sum1, 1);
        sum1 += __shfl_xor_sync(0xffffffff, sum1, 2);
        l0 = l0 * corr0 + sum0;
        l1 = l1 * corr1 + sum1;

#pragma unroll
        for (int j = 0; j < 8; j++) {
            accO[j][0] *= corr0; accO[j][1] *= corr0;
            accO[j][2] *= corr1; accO[j][3] *= corr1;
        }
        __syncwarp();

        // ---- O += P @ V  (A from Ps, B from Vts[d][key]) ----
#pragma unroll
        for (int ks = 0; ks < 8; ks++) {
            uint32_t pa[4];
            ldsm4(pa, pAddr0 + ks * 32);
#pragma unroll
            for (int jp = 0; jp < 4; jp++) {
                uint32_t bf[4];
                ldsm4(bf, vAddr0 + (jp * 16 * AQS + ks * 8) * 4);
                mma_tf32(accO[jp * 2],     pa, bf);
                mma_tf32(accO[jp * 2 + 1], pa, bf + 2);
            }
        }
    }

    // ---- epilogue ----
    float inv0 = 1.f / l0, inv1 = 1.f / l1;
    const int r0 = b * T_SEQ + qb * 128 + w * 16 + g;
#pragma unroll
    for (int j = 0; j < 8; j++) {
        int c = h * HD + j * 8 + 2 * tig;
        float2 o0 = make_float2(to_tf32(accO[j][0] * inv0), to_tf32(accO[j][1] * inv0));
        float2 o1 = make_float2(to_tf32(accO[j][2] * inv1), to_tf32(accO[j][3] * inv1));
        *(float2*)&out[(size_t)r0 * HDIM + c] = o0;
        *(float2*)&out[(size_t)(r0 + 8) * HDIM + c] = o1;
    }
}

// ---------------------------------------------------------------------------
// Launch
// ---------------------------------------------------------------------------
extern "C" void kernel_launch(void* const* d_in, const int* in_sizes, int n_in,
                              void* d_out, int out_size)
{
    const float* hidden = (const float*)d_in[0];
    const int*   amask  = (const int*)d_in[1];
    const float* w_qkv  = (const float*)d_in[2];
    const float* b_qkv  = (const float*)d_in[3];
    const float* w_out  = (const float*)d_in[4];
    float* out = (float*)d_out;

    float *qkv, *Q, *K, *V, *attn, *Ar, *Bt1, *Bt2;
    cudaGetSymbolAddress((void**)&qkv,  g_qkv);
    cudaGetSymbolAddress((void**)&Q,    g_Q);
    cudaGetSymbolAddress((void**)&K,    g_K);
    cudaGetSymbolAddress((void**)&V,    g_V);
    cudaGetSymbolAddress((void**)&attn, g_attn);
    cudaGetSymbolAddress((void**)&Ar,   g_Ar);
    cudaGetSymbolAddress((void**)&Bt1,  g_Bt1);
    cudaGetSymbolAddress((void**)&Bt2,  g_Bt2);

    cudaFuncSetAttribute(attn_mma_kernel, cudaFuncAttributeMaxDynamicSharedMemorySize,
                         ATT_SMEM);
    cudaFuncSetAttribute(tf32_mma_gemm, cudaFuncAttributeMaxDynamicSharedMemorySize,
                         GEMM_SMEM);

    // 0) tf32-round A; transpose+round weights
    round_tf32_kernel<<<MROWS * HDIM / 4 / 256, 256>>>(hidden, Ar);
    transpose_round_kernel<<<dim3(3 * HDIM / 32, HDIM / 32), 256>>>(w_qkv, Bt1, HDIM, 3 * HDIM);
    transpose_round_kernel<<<dim3(HDIM / 32, HDIM / 32), 256>>>(w_out, Bt2, HDIM, HDIM);

    // 1) qkv = Ar @ w_qkv + b_qkv (tf32 mma.sync + ldmatrix)
    tf32_mma_gemm<<<dim3(3 * HDIM / 128, MROWS / 128), 256, GEMM_SMEM>>>(
        Ar, Bt1, b_qkv, qkv, 3 * HDIM, HDIM);

    // 2) RoPE (Q/K) + V transpose
    rope_kernel<<<MROWS, 256>>>(qkv, Q, K);
    vtrans_kernel<<<dim3(T_SEQ / 32, HD / 32, BATCH * NHEAD), 256>>>(qkv, V);

    // 3) tf32 mma flash attention -> attn [B,T,H] (tf32-rounded)
    attn_mma_kernel<<<dim3(T_SEQ / 128, BATCH * NHEAD), 256, ATT_SMEM>>>(
        Q, K, V, amask, attn);

    // 4) out = attn @ w_out (tf32 mma.sync + ldmatrix)
    tf32_mma_gemm<<<dim3(HDIM / 128, MROWS / 128), 256, GEMM_SMEM>>>(
        attn, Bt2, nullptr, out, HDIM, HDIM);
}